// round 4
// baseline (speedup 1.0000x reference)
#include <cuda_runtime.h>
#include <cstdint>

#define OUT_F 28672
#define IN_F  8192
#define ROW_UINT4 1024            // 4096 int32 per row / 4
#define RPB 8                     // rows per block = warps per block

// qweight is int32 (harness widened uint8): each element is a byte value
// 0..255 holding two 4-bit codes (lo nibble = even column, hi = odd column).
//
// Row-per-warp: warp w of block b owns output row b*8+w and streams its whole
// 16 KB slice in 32 iterations. Iter i, lane l loads uint4 index 32i+l of the
// row -> ints 4*(32i+l)..+3 -> columns 256i+8l..+7. The matching 8 x-floats
// come from L1 (x is 32 KB, resident). Accumulators persist in registers over
// all iterations; a single 5-level shuffle reduce per row at the end.

__global__ __launch_bounds__(256)
void q3_matvec_kernel(const float* __restrict__ x,
                      const int* __restrict__ qw,
                      const float* __restrict__ kv,
                      const float* __restrict__ bias,
                      float* __restrict__ y)
{
    __shared__ float s_lut[RPB * 16];   // 8 row-LUTs; 16 words -> 16 banks, conflict-free

    const int t = threadIdx.x;
    const int w = t >> 5;
    const int l = t & 31;
    const int row = blockIdx.x * RPB + w;

    if (t < RPB * 16)
        s_lut[t] = kv[blockIdx.x * (RPB * 16) + t];
    __syncthreads();

    const float* lut = s_lut + (w << 4);
    const uint4* qp = reinterpret_cast<const uint4*>(qw) + (size_t)row * ROW_UINT4 + l;
    const float4* xp = reinterpret_cast<const float4*>(x) + (l << 1);

    float a0 = 0.f, a1 = 0.f, a2 = 0.f, a3 = 0.f;

    #pragma unroll 4
    for (int i = 0; i < 32; i++) {
        const uint4  q  = qp[i << 5];          // 512 B/warp from DRAM stream
        const float4 xa = xp[(i << 6)];        // x: L1-resident
        const float4 xb = xp[(i << 6) + 1];

        // v <= 255, so (v >> 4) is already a clean 4-bit code (no mask).
        a0 = fmaf(lut[q.x & 15u], xa.x, a0);
        a1 = fmaf(lut[q.x >> 4],  xa.y, a1);
        a2 = fmaf(lut[q.y & 15u], xa.z, a2);
        a3 = fmaf(lut[q.y >> 4],  xa.w, a3);
        a0 = fmaf(lut[q.z & 15u], xb.x, a0);
        a1 = fmaf(lut[q.z >> 4],  xb.y, a1);
        a2 = fmaf(lut[q.w & 15u], xb.z, a2);
        a3 = fmaf(lut[q.w >> 4],  xb.w, a3);
    }

    // One reduction per row, at the very end.
    float acc = (a0 + a1) + (a2 + a3);
    #pragma unroll
    for (int s = 16; s > 0; s >>= 1)
        acc += __shfl_xor_sync(0xffffffffu, acc, s);

    if (l == 0)
        y[row] = acc + bias[row];
}

extern "C" void kernel_launch(void* const* d_in, const int* in_sizes, int n_in,
                              void* d_out, int out_size)
{
    const float* x    = (const float*)d_in[0];
    const int*   qw   = (const int*)d_in[1];
    const float* kv   = (const float*)d_in[2];
    const float* bias = (const float*)d_in[3];
    float*       y    = (float*)d_out;

    dim3 grid(OUT_F / RPB);   // 3584 blocks of 8 warps (one row per warp)
    dim3 block(256);
    q3_matvec_kernel<<<grid, block>>>(x, qw, kv, bias, y);
}

// round 6
// speedup vs baseline: 1.0667x; 1.0667x over previous
#include <cuda_runtime.h>
#include <cstdint>

#define OUT_F 28672
#define IN_F  8192
#define ROW_UINT4 1024            // 4096 int32 per row / 4
#define NW  4                     // warps per block
#define RPW 4                     // rows per warp
#define RPB (NW * RPW)            // 16 rows per block

// qweight is int32 (harness-widened uint8): each element is one byte value
// 0..255 = two 4-bit codes (lo nibble -> even column, hi nibble -> odd).
//
// Warp w owns 4 consecutive rows r0..r0+3 (r0 = block*16 + 4w) and streams all
// four contiguously: iter i, lane l loads the uint4 at row*1024 + 32i + l from
// each row (4 independent contiguous 16 KB streams -> good HBM locality), plus
// ONE shared x window (columns 256i+8l..+7, L1-resident) used by all 4 rows.
// Accumulators stay in registers for all 32 iterations; 4 shuffle reductions
// per warp at the end.

__global__ __launch_bounds__(128)
void q3_matvec_kernel(const float* __restrict__ x,
                      const int* __restrict__ qw,
                      const float* __restrict__ kv,
                      const float* __restrict__ bias,
                      float* __restrict__ y)
{
    __shared__ float s_lut[RPB * 16];   // 16 row-LUTs = 256 floats (1 KB)

    const int t = threadIdx.x;
    const int w = t >> 5;
    const int l = t & 31;
    const int rbase = blockIdx.x * RPB;        // first row of block
    const int wrow = rbase + w * RPW;          // first row of this warp

    // Stage 256 LUT floats with 128 threads: two per thread. (R5 bug: only 128
    // were staged, leaving rows 8-15 with garbage.)
    s_lut[t]       = kv[rbase * 16 + t];
    s_lut[t + 128] = kv[rbase * 16 + t + 128];
    __syncthreads();

    const float* lut0 = s_lut + (w * RPW) * 16;
    const uint4* qp = reinterpret_cast<const uint4*>(qw)
                    + (size_t)wrow * ROW_UINT4 + l;
    const float4* xp = reinterpret_cast<const float4*>(x) + (l << 1);

    float a00 = 0.f, a01 = 0.f;   // row +0
    float a10 = 0.f, a11 = 0.f;   // row +1
    float a20 = 0.f, a21 = 0.f;   // row +2
    float a30 = 0.f, a31 = 0.f;   // row +3

    #pragma unroll 2
    for (int i = 0; i < 32; i++) {
        // 4 independent contiguous DRAM streams (one per row), 16 B/lane each.
        const uint4 q0 = qp[(i << 5)];
        const uint4 q1 = qp[(i << 5) + 1 * ROW_UINT4];
        const uint4 q2 = qp[(i << 5) + 2 * ROW_UINT4];
        const uint4 q3 = qp[(i << 5) + 3 * ROW_UINT4];
        // One shared x window for all 4 rows (L1-resident after first touch).
        const float4 xa = xp[(i << 6)];
        const float4 xb = xp[(i << 6) + 1];

        // v <= 255 so (v >> 4) is already a clean code (no mask needed).
        #define DO_ROW(Q, LUT, A0, A1)                        \
            A0 = fmaf((LUT)[(Q).x & 15u], xa.x, A0);          \
            A1 = fmaf((LUT)[(Q).x >> 4],  xa.y, A1);          \
            A0 = fmaf((LUT)[(Q).y & 15u], xa.z, A0);          \
            A1 = fmaf((LUT)[(Q).y >> 4],  xa.w, A1);          \
            A0 = fmaf((LUT)[(Q).z & 15u], xb.x, A0);          \
            A1 = fmaf((LUT)[(Q).z >> 4],  xb.y, A1);          \
            A0 = fmaf((LUT)[(Q).w & 15u], xb.z, A0);          \
            A1 = fmaf((LUT)[(Q).w >> 4],  xb.w, A1);

        DO_ROW(q0, lut0,      a00, a01)
        DO_ROW(q1, lut0 + 16, a10, a11)
        DO_ROW(q2, lut0 + 32, a20, a21)
        DO_ROW(q3, lut0 + 48, a30, a31)
        #undef DO_ROW
    }

    // Four reductions per warp, once at the end.
    float r0 = a00 + a01;
    float r1 = a10 + a11;
    float r2 = a20 + a21;
    float r3 = a30 + a31;
    #pragma unroll
    for (int s = 16; s > 0; s >>= 1) {
        r0 += __shfl_xor_sync(0xffffffffu, r0, s);
        r1 += __shfl_xor_sync(0xffffffffu, r1, s);
        r2 += __shfl_xor_sync(0xffffffffu, r2, s);
        r3 += __shfl_xor_sync(0xffffffffu, r3, s);
    }
    if (l == 0) {
        y[wrow + 0] = r0 + bias[wrow + 0];
        y[wrow + 1] = r1 + bias[wrow + 1];
        y[wrow + 2] = r2 + bias[wrow + 2];
        y[wrow + 3] = r3 + bias[wrow + 3];
    }
}

extern "C" void kernel_launch(void* const* d_in, const int* in_sizes, int n_in,
                              void* d_out, int out_size)
{
    const float* x    = (const float*)d_in[0];
    const int*   qw   = (const int*)d_in[1];
    const float* kv   = (const float*)d_in[2];
    const float* bias = (const float*)d_in[3];
    float*       y    = (float*)d_out;

    dim3 grid(OUT_F / RPB);   // 1792 blocks of 4 warps (4 rows per warp)
    dim3 block(128);
    q3_matvec_kernel<<<grid, block>>>(x, qw, kv, bias, y);
}

// round 7
// speedup vs baseline: 1.1451x; 1.0735x over previous
#include <cuda_runtime.h>
#include <cstdint>

#define OUT_F 28672
#define IN_F  8192
#define ROW_BYTES 16384          // int32-widened qweight row: 4096 * 4 B
#define RPB 32                   // rows per block
#define NW  8                    // warps per block (4 rows each)
#define CHUNK_B 512              // bytes per row per stage
#define NCHUNK (ROW_BYTES / CHUNK_B)   // 32
#define STAGE_B (RPB * CHUNK_B)        // 16 KB per stage

// qweight is int32 (harness-widened uint8): each element is a byte value
// 0..255 = two 4-bit codes (lo nibble -> even column, hi nibble -> odd).
//
// Pipeline: double-buffered 16 KB stages filled by cp.async.bulk (32 copies of
// 512 B, one per row) with mbarrier expect_tx completion. This keeps ~16 KB in
// flight per block (~96 KB/SM at 6 blocks) independent of ptxas scheduling —
// the LDG versions never exceeded ~6 KB/SM and sat latency-bound at 62-73% of
// HBM. Consumers: warp w owns rows 4w..4w+3; per chunk, lane l reads the uint4
// at byte l*16 of each row slice (conflict-free LDS.128), looks nibbles up in
// a 16-entry smem LUT (conflict-free by construction), x window from L1.

__device__ __forceinline__ uint32_t smem_u32(const void* p) {
    return (uint32_t)__cvta_generic_to_shared(p);
}

__device__ __forceinline__ void mbar_init(uint32_t mbar, uint32_t count) {
    asm volatile("mbarrier.init.shared.b64 [%0], %1;" :: "r"(mbar), "r"(count) : "memory");
}
__device__ __forceinline__ void mbar_expect_tx(uint32_t mbar, uint32_t bytes) {
    asm volatile("mbarrier.arrive.expect_tx.shared.b64 _, [%0], %1;"
                 :: "r"(mbar), "r"(bytes) : "memory");
}
__device__ __forceinline__ void bulk_g2s(uint32_t dst, const void* src,
                                         uint32_t bytes, uint32_t mbar) {
    asm volatile(
        "cp.async.bulk.shared::cluster.global.mbarrier::complete_tx::bytes "
        "[%0], [%1], %2, [%3];"
        :: "r"(dst), "l"(src), "r"(bytes), "r"(mbar) : "memory");
}
__device__ __forceinline__ void mbar_wait(uint32_t mbar, uint32_t parity) {
    uint32_t done;
    asm volatile(
        "{\n\t.reg .pred p;\n\t"
        "mbarrier.try_wait.parity.acquire.cta.shared::cta.b64 p, [%1], %2;\n\t"
        "selp.b32 %0, 1, 0, p;\n\t}"
        : "=r"(done) : "r"(mbar), "r"(parity) : "memory");
    if (!done) {
        asm volatile(
            "{\n\t.reg .pred P1;\n\t"
            "WL_%=:\n\t"
            "mbarrier.try_wait.parity.acquire.cta.shared::cta.b64 P1, [%0], %1, 0x989680;\n\t"
            "@P1 bra.uni WD_%=;\n\t"
            "bra.uni WL_%=;\n\t"
            "WD_%=:\n\t}"
            :: "r"(mbar), "r"(parity) : "memory");
    }
}

__global__ __launch_bounds__(256, 6)
void q3_matvec_kernel(const float* __restrict__ x,
                      const int* __restrict__ qw,
                      const float* __restrict__ kv,
                      const float* __restrict__ bias,
                      float* __restrict__ y)
{
    __shared__ alignas(16) uint8_t s_buf[2][STAGE_B];   // 2 x 16 KB stages
    __shared__ float s_lut[RPB * 16];                   // 32 row-LUTs (2 KB)
    __shared__ alignas(8) uint64_t s_mbar[2];

    const int t = threadIdx.x;
    const int w = t >> 5;
    const int l = t & 31;
    const int rbase = blockIdx.x * RPB;
    const int wrow = rbase + (w << 2);      // first of this warp's 4 rows

    // Stage 512 LUT floats (2 per thread).
    s_lut[t]       = kv[rbase * 16 + t];
    s_lut[t + 256] = kv[rbase * 16 + t + 256];

    const uint32_t mb0 = smem_u32(&s_mbar[0]);
    const uint32_t mb1 = smem_u32(&s_mbar[1]);
    const uint32_t bu0 = smem_u32(&s_buf[0][0]);
    const uint32_t bu1 = smem_u32(&s_buf[1][0]);

    if (t == 0) { mbar_init(mb0, 1); mbar_init(mb1, 1); }
    __syncthreads();

    const char* gq = (const char*)qw + (size_t)rbase * ROW_BYTES;

    // Prologue: fill both stages (chunks 0 and 1).
    if (t == 0) {
        mbar_expect_tx(mb0, STAGE_B);
        #pragma unroll 4
        for (int r = 0; r < RPB; r++)
            bulk_g2s(bu0 + r * CHUNK_B, gq + (size_t)r * ROW_BYTES, CHUNK_B, mb0);
        mbar_expect_tx(mb1, STAGE_B);
        #pragma unroll 4
        for (int r = 0; r < RPB; r++)
            bulk_g2s(bu1 + r * CHUNK_B, gq + (size_t)r * ROW_BYTES + CHUNK_B, CHUNK_B, mb1);
    }

    const float* lut0 = s_lut + (w << 2) * 16;
    const float4* xp = reinterpret_cast<const float4*>(x);

    float a00 = 0.f, a01 = 0.f;
    float a10 = 0.f, a11 = 0.f;
    float a20 = 0.f, a21 = 0.f;
    float a30 = 0.f, a31 = 0.f;

    #pragma unroll 1
    for (int c = 0; c < NCHUNK; c++) {
        const int st = c & 1;
        const uint32_t mb = st ? mb1 : mb0;
        mbar_wait(mb, (c >> 1) & 1);

        // x window for this chunk: columns c*256 + 8l .. +7 (L1-resident).
        const float4 xa = xp[(c << 6) + (l << 1)];
        const float4 xb = xp[(c << 6) + (l << 1) + 1];

        const uint8_t* buf = s_buf[st] + ((w << 2) * CHUNK_B) + (l << 4);

        const uint4 q0 = *reinterpret_cast<const uint4*>(buf);
        const uint4 q1 = *reinterpret_cast<const uint4*>(buf + CHUNK_B);
        const uint4 q2 = *reinterpret_cast<const uint4*>(buf + 2 * CHUNK_B);
        const uint4 q3 = *reinterpret_cast<const uint4*>(buf + 3 * CHUNK_B);

        // v <= 255 so (v >> 4) is already a clean code (no mask).
        #define DO_ROW(Q, LUT, A0, A1)                        \
            A0 = fmaf((LUT)[(Q).x & 15u], xa.x, A0);          \
            A1 = fmaf((LUT)[(Q).x >> 4],  xa.y, A1);          \
            A0 = fmaf((LUT)[(Q).y & 15u], xa.z, A0);          \
            A1 = fmaf((LUT)[(Q).y >> 4],  xa.w, A1);          \
            A0 = fmaf((LUT)[(Q).z & 15u], xb.x, A0);          \
            A1 = fmaf((LUT)[(Q).z >> 4],  xb.y, A1);          \
            A0 = fmaf((LUT)[(Q).w & 15u], xb.z, A0);          \
            A1 = fmaf((LUT)[(Q).w >> 4],  xb.w, A1);

        DO_ROW(q0, lut0,      a00, a01)
        DO_ROW(q1, lut0 + 16, a10, a11)
        DO_ROW(q2, lut0 + 32, a20, a21)
        DO_ROW(q3, lut0 + 48, a30, a31)
        #undef DO_ROW

        __syncthreads();   // all warps done reading stage st

        if (t == 0 && c + 2 < NCHUNK) {
            const uint32_t bu = st ? bu1 : bu0;
            mbar_expect_tx(mb, STAGE_B);
            const char* src = gq + (size_t)(c + 2) * CHUNK_B;
            #pragma unroll 4
            for (int r = 0; r < RPB; r++)
                bulk_g2s(bu + r * CHUNK_B, src + (size_t)r * ROW_BYTES, CHUNK_B, mb);
        }
    }

    // Four reductions per warp, once.
    float r0 = a00 + a01;
    float r1 = a10 + a11;
    float r2 = a20 + a21;
    float r3 = a30 + a31;
    #pragma unroll
    for (int s = 16; s > 0; s >>= 1) {
        r0 += __shfl_xor_sync(0xffffffffu, r0, s);
        r1 += __shfl_xor_sync(0xffffffffu, r1, s);
        r2 += __shfl_xor_sync(0xffffffffu, r2, s);
        r3 += __shfl_xor_sync(0xffffffffu, r3, s);
    }
    if (l == 0) {
        y[wrow + 0] = r0 + bias[wrow + 0];
        y[wrow + 1] = r1 + bias[wrow + 1];
        y[wrow + 2] = r2 + bias[wrow + 2];
        y[wrow + 3] = r3 + bias[wrow + 3];
    }
}

extern "C" void kernel_launch(void* const* d_in, const int* in_sizes, int n_in,
                              void* d_out, int out_size)
{
    const float* x    = (const float*)d_in[0];
    const int*   qw   = (const int*)d_in[1];
    const float* kv   = (const float*)d_in[2];
    const float* bias = (const float*)d_in[3];
    float*       y    = (float*)d_out;

    dim3 grid(OUT_F / RPB);   // 896 blocks of 8 warps (32 rows per block)
    dim3 block(256);
    q3_matvec_kernel<<<grid, block>>>(x, qw, kv, bias, y);
}

// round 8
// speedup vs baseline: 1.2121x; 1.0585x over previous
#include <cuda_runtime.h>
#include <cstdint>

#define OUT_F 28672
#define IN_F  8192
#define ROW_BYTES 16384            // int32-widened qweight row: 4096 * 4 B
#define RPB 32                     // rows per block
#define CHUNK_B 1024               // bytes per row per stage
#define NCHUNK (ROW_BYTES / CHUNK_B)   // 16
#define STAGE_B (RPB * CHUNK_B)        // 32 KB per stage

// qweight is int32 (harness-widened uint8): each element is a byte value
// 0..255 = two 4-bit codes (lo nibble -> even column, hi nibble -> odd).
//
// Double-buffered 32 KB stages filled by cp.async.bulk. Refill is issued by 32
// threads in parallel (one 1 KB copy per row each) instead of one serial
// thread — removes ~0.3us/chunk of producer serialization from the critical
// path. 1 KB contiguous requests double DRAM burst locality vs R7's 512 B.

__device__ __forceinline__ uint32_t smem_u32(const void* p) {
    return (uint32_t)__cvta_generic_to_shared(p);
}
__device__ __forceinline__ void mbar_init(uint32_t mbar, uint32_t count) {
    asm volatile("mbarrier.init.shared.b64 [%0], %1;" :: "r"(mbar), "r"(count) : "memory");
}
__device__ __forceinline__ void mbar_expect_tx(uint32_t mbar, uint32_t bytes) {
    asm volatile("mbarrier.arrive.expect_tx.shared.b64 _, [%0], %1;"
                 :: "r"(mbar), "r"(bytes) : "memory");
}
__device__ __forceinline__ void bulk_g2s(uint32_t dst, const void* src,
                                         uint32_t bytes, uint32_t mbar) {
    asm volatile(
        "cp.async.bulk.shared::cluster.global.mbarrier::complete_tx::bytes "
        "[%0], [%1], %2, [%3];"
        :: "r"(dst), "l"(src), "r"(bytes), "r"(mbar) : "memory");
}
__device__ __forceinline__ void mbar_wait(uint32_t mbar, uint32_t parity) {
    uint32_t done;
    asm volatile(
        "{\n\t.reg .pred p;\n\t"
        "mbarrier.try_wait.parity.acquire.cta.shared::cta.b64 p, [%1], %2;\n\t"
        "selp.b32 %0, 1, 0, p;\n\t}"
        : "=r"(done) : "r"(mbar), "r"(parity) : "memory");
    if (!done) {
        asm volatile(
            "{\n\t.reg .pred P1;\n\t"
            "WL_%=:\n\t"
            "mbarrier.try_wait.parity.acquire.cta.shared::cta.b64 P1, [%0], %1, 0x989680;\n\t"
            "@P1 bra.uni WD_%=;\n\t"
            "bra.uni WL_%=;\n\t"
            "WD_%=:\n\t}"
            :: "r"(mbar), "r"(parity) : "memory");
    }
}

__global__ __launch_bounds__(256, 3)
void q3_matvec_kernel(const float* __restrict__ x,
                      const int* __restrict__ qw,
                      const float* __restrict__ kv,
                      const float* __restrict__ bias,
                      float* __restrict__ y)
{
    __shared__ alignas(16) uint8_t s_buf[2][STAGE_B];   // 2 x 32 KB
    __shared__ float s_lut[RPB * 16];                   // 32 row-LUTs (2 KB)
    __shared__ alignas(8) uint64_t s_mbar[2];

    const int t = threadIdx.x;
    const int w = t >> 5;
    const int l = t & 31;
    const int rbase = blockIdx.x * RPB;
    const int wrow = rbase + (w << 2);

    // Stage 512 LUT floats (2 per thread).
    s_lut[t]       = kv[rbase * 16 + t];
    s_lut[t + 256] = kv[rbase * 16 + t + 256];

    const uint32_t mb0 = smem_u32(&s_mbar[0]);
    const uint32_t mb1 = smem_u32(&s_mbar[1]);
    const uint32_t bu0 = smem_u32(&s_buf[0][0]);
    const uint32_t bu1 = smem_u32(&s_buf[1][0]);

    if (t == 0) { mbar_init(mb0, 1); mbar_init(mb1, 1); }
    __syncthreads();

    const char* gq = (const char*)qw + (size_t)rbase * ROW_BYTES;

    // Prologue: fill both stages (chunks 0 and 1), 32 parallel issuers.
    if (t == 0) { mbar_expect_tx(mb0, STAGE_B); mbar_expect_tx(mb1, STAGE_B); }
    if (t < 32) {
        __syncwarp();
        const char* rowp = gq + (size_t)t * ROW_BYTES;
        bulk_g2s(bu0 + t * CHUNK_B, rowp,           CHUNK_B, mb0);
        bulk_g2s(bu1 + t * CHUNK_B, rowp + CHUNK_B, CHUNK_B, mb1);
    }

    const float* lut0 = s_lut + (w << 2) * 16;
    const float4* xp = reinterpret_cast<const float4*>(x);

    float a00 = 0.f, a01 = 0.f;
    float a10 = 0.f, a11 = 0.f;
    float a20 = 0.f, a21 = 0.f;
    float a30 = 0.f, a31 = 0.f;

    #pragma unroll 1
    for (int c = 0; c < NCHUNK; c++) {
        const int st = c & 1;
        const uint32_t mb = st ? mb1 : mb0;
        mbar_wait(mb, (c >> 1) & 1);

        const uint8_t* wbuf = s_buf[st] + ((w << 2) * CHUNK_B);

        // Two 512 B half-chunks per row; x window per half from L1.
        #pragma unroll
        for (int h = 0; h < 2; h++) {
            const float4 xa = xp[(c << 7) + (h << 6) + (l << 1)];
            const float4 xb = xp[(c << 7) + (h << 6) + (l << 1) + 1];
            const uint8_t* buf = wbuf + (h << 9) + (l << 4);

            const uint4 q0 = *reinterpret_cast<const uint4*>(buf);
            const uint4 q1 = *reinterpret_cast<const uint4*>(buf + CHUNK_B);
            const uint4 q2 = *reinterpret_cast<const uint4*>(buf + 2 * CHUNK_B);
            const uint4 q3 = *reinterpret_cast<const uint4*>(buf + 3 * CHUNK_B);

            // v <= 255 so (v >> 4) is already a clean code (no mask).
            #define DO_ROW(Q, LUT, A0, A1)                        \
                A0 = fmaf((LUT)[(Q).x & 15u], xa.x, A0);          \
                A1 = fmaf((LUT)[(Q).x >> 4],  xa.y, A1);          \
                A0 = fmaf((LUT)[(Q).y & 15u], xa.z, A0);          \
                A1 = fmaf((LUT)[(Q).y >> 4],  xa.w, A1);          \
                A0 = fmaf((LUT)[(Q).z & 15u], xb.x, A0);          \
                A1 = fmaf((LUT)[(Q).z >> 4],  xb.y, A1);          \
                A0 = fmaf((LUT)[(Q).w & 15u], xb.z, A0);          \
                A1 = fmaf((LUT)[(Q).w >> 4],  xb.w, A1);

            DO_ROW(q0, lut0,      a00, a01)
            DO_ROW(q1, lut0 + 16, a10, a11)
            DO_ROW(q2, lut0 + 32, a20, a21)
            DO_ROW(q3, lut0 + 48, a30, a31)
            #undef DO_ROW
        }

        __syncthreads();   // stage st fully consumed by all warps

        if (c + 2 < NCHUNK) {
            if (t == 0) mbar_expect_tx(mb, STAGE_B);
            if (t < 32) {
                __syncwarp();
                const uint32_t bu = st ? bu1 : bu0;
                bulk_g2s(bu + t * CHUNK_B,
                         gq + (size_t)t * ROW_BYTES + (size_t)(c + 2) * CHUNK_B,
                         CHUNK_B, mb);
            }
        }
    }

    // Four reductions per warp, once.
    float r0 = a00 + a01;
    float r1 = a10 + a11;
    float r2 = a20 + a21;
    float r3 = a30 + a31;
    #pragma unroll
    for (int s = 16; s > 0; s >>= 1) {
        r0 += __shfl_xor_sync(0xffffffffu, r0, s);
        r1 += __shfl_xor_sync(0xffffffffu, r1, s);
        r2 += __shfl_xor_sync(0xffffffffu, r2, s);
        r3 += __shfl_xor_sync(0xffffffffu, r3, s);
    }
    if (l == 0) {
        y[wrow + 0] = r0 + bias[wrow + 0];
        y[wrow + 1] = r1 + bias[wrow + 1];
        y[wrow + 2] = r2 + bias[wrow + 2];
        y[wrow + 3] = r3 + bias[wrow + 3];
    }
}

extern "C" void kernel_launch(void* const* d_in, const int* in_sizes, int n_in,
                              void* d_out, int out_size)
{
    const float* x    = (const float*)d_in[0];
    const int*   qw   = (const int*)d_in[1];
    const float* kv   = (const float*)d_in[2];
    const float* bias = (const float*)d_in[3];
    float*       y    = (float*)d_out;

    dim3 grid(OUT_F / RPB);   // 896 blocks
    dim3 block(256);
    q3_matvec_kernel<<<grid, block>>>(x, qw, kv, bias, y);
}